// round 1
// baseline (speedup 1.0000x reference)
#include <cuda_runtime.h>

// Problem constants
#define TT   9
#define BB   8
#define CC   256
#define HWHW 3136          // 56*56
#define PIX  8             // pixels per block tile
#define NTHREADS 256
#define TILES_PER_B (HWHW / PIX)   // 392
#define NCG 32             // c-groups = NTHREADS / PIX

// Shared memory layout (floats):
//   tile : [TT*CC][PIX]      = 18432
//   wc   : [CC]              =   256
//   wo   : [CC]              =   256
//   part : [TT+1][NCG][PIX]  =  2560
//   scor : [TT][PIX]         =    72   (scores, then attn weights)
//   cent : [PIX]             =     8
#define SMEM_FLOATS (TT*CC*PIX + CC + CC + (TT+1)*NCG*PIX + TT*PIX + PIX)
#define SMEM_BYTES  (SMEM_FLOATS * 4)

__global__ __launch_bounds__(NTHREADS, 2)
void tfma_kernel(const float* __restrict__ seq,
                 const float* __restrict__ w,
                 const float* __restrict__ bptr,
                 const float* __restrict__ gptr,
                 float* __restrict__ out)
{
    extern __shared__ float sm[];
    float* tile = sm;                              // [TT*CC][PIX]
    float* wc   = tile + TT*CC*PIX;                // [CC]
    float* wo   = wc + CC;                         // [CC]
    float* part = wo + CC;                         // [(TT+1)][NCG][PIX]
    float* scor = part + (TT+1)*NCG*PIX;           // [TT][PIX]
    float* cent = scor + TT*PIX;                   // [PIX]

    const int tid     = threadIdx.x;
    const int bidx    = blockIdx.x / TILES_PER_B;
    const int tileIdx = blockIdx.x % TILES_PER_B;
    const int pix0    = tileIdx * PIX;

    // ---- stage weights ----
    wc[tid] = w[tid];          // w_center = w[0:256]
    wo[tid] = w[CC + tid];     // w_other  = w[256:512]

    // ---- stage the [T, C, PIX] slab into SMEM, coalesced float4 ----
    // global: seq[t][b][c][hw];  row (t,c) covers PIX=8 contiguous floats = 2 float4
    {
        const float* base = seq + (size_t)bidx * CC * HWHW + pix0;
        const int q  = tid & 1;        // which float4 of the 8-float row
        const int r0 = tid >> 1;       // row index within a pass (128 rows/pass)
        #pragma unroll
        for (int it = 0; it < (TT*CC)/128; ++it) {   // 18 passes
            const int r = r0 + it * 128;             // r = t*CC + c
            const int t = r >> 8;
            const int c = r & (CC - 1);
            const float4 v = *(const float4*)(base + (size_t)t * BB * CC * HWHW
                                                   + (size_t)c * HWHW + q * 4);
            *(float4*)(tile + r * PIX + q * 4) = v;
        }
    }
    __syncthreads();

    // ---- phase 2: partial score reductions over C ----
    // thread = (cg, p); each thread covers c = cg + 32*ci (conflict-free LDS)
    const int p  = tid & (PIX - 1);
    const int cg = tid >> 3;           // 0..31

    {
        float acc[TT];
        float accc = 0.f;
        #pragma unroll
        for (int t = 0; t < TT; ++t) acc[t] = 0.f;

        #pragma unroll
        for (int ci = 0; ci < CC / NCG; ++ci) {      // 8 iterations
            const int c  = cg + ci * NCG;
            const float wot = wo[c];
            const float wct = wc[c];
            #pragma unroll
            for (int t = 0; t < TT; ++t) {
                const float v = tile[(t * CC + c) * PIX + p];
                acc[t] = fmaf(v, wot, acc[t]);
                if (t == TT / 2) accc = fmaf(v, wct, accc);
            }
        }
        #pragma unroll
        for (int t = 0; t < TT; ++t)
            part[(t * NCG + cg) * PIX + p] = acc[t];
        part[(TT * NCG + cg) * PIX + p] = accc;
    }
    __syncthreads();

    // ---- reduce partials across the 32 c-groups ----
    if (tid < TT * PIX) {
        const int t  = tid / PIX;
        const int pp = tid % PIX;
        float s = 0.f;
        #pragma unroll
        for (int g = 0; g < NCG; ++g) s += part[(t * NCG + g) * PIX + pp];
        scor[t * PIX + pp] = s;
    } else if (tid < TT * PIX + PIX) {
        const int pp = tid - TT * PIX;
        float s = 0.f;
        #pragma unroll
        for (int g = 0; g < NCG; ++g) s += part[(TT * NCG + g) * PIX + pp];
        cent[pp] = s;
    }
    __syncthreads();

    // ---- softmax over T per pixel (8 threads) ----
    if (tid < PIX) {
        const float bv = bptr[0];
        const float cv = cent[tid];
        float sc[TT];
        float m = -1e30f;
        #pragma unroll
        for (int t = 0; t < TT; ++t) {
            sc[t] = scor[t * PIX + tid] + cv + bv;
            m = fmaxf(m, sc[t]);
        }
        float sum = 0.f;
        #pragma unroll
        for (int t = 0; t < TT; ++t) {
            sc[t] = __expf(sc[t] - m);
            sum += sc[t];
        }
        const float inv = 1.f / sum;
        #pragma unroll
        for (int t = 0; t < TT; ++t)
            scor[t * PIX + tid] = sc[t] * inv;     // now holds attn weights
    }
    __syncthreads();

    // ---- phase 3: attended sum + residual, write out ----
    {
        float a[TT];
        #pragma unroll
        for (int t = 0; t < TT; ++t) a[t] = scor[t * PIX + p];   // broadcast LDS
        const float gamma = gptr[0];
        float* obase = out + (size_t)bidx * CC * HWHW + pix0 + p;

        #pragma unroll
        for (int k = 0; k < CC / NCG; ++k) {        // 8 outputs per thread
            const int c = cg + k * NCG;
            float s  = 0.f;
            float cv = 0.f;
            #pragma unroll
            for (int t = 0; t < TT; ++t) {
                const float v = tile[(t * CC + c) * PIX + p];
                s = fmaf(a[t], v, s);
                if (t == TT / 2) cv = v;
            }
            obase[(size_t)c * HWHW] = cv + gamma * s;
        }
    }
}

extern "C" void kernel_launch(void* const* d_in, const int* in_sizes, int n_in,
                              void* d_out, int out_size)
{
    (void)in_sizes; (void)n_in; (void)out_size;
    const float* seq   = (const float*)d_in[0];
    const float* w     = (const float*)d_in[1];
    const float* bv    = (const float*)d_in[2];
    const float* gamma = (const float*)d_in[3];
    float* out = (float*)d_out;

    cudaFuncSetAttribute(tfma_kernel,
                         cudaFuncAttributeMaxDynamicSharedMemorySize, SMEM_BYTES);

    tfma_kernel<<<BB * TILES_PER_B, NTHREADS, SMEM_BYTES>>>(seq, w, bv, gamma, out);
}

// round 2
// speedup vs baseline: 1.5797x; 1.5797x over previous
#include <cuda_runtime.h>
#include <cstdint>

// Problem constants
#define TT    9
#define BB    8
#define CC    256
#define HWHW  3136          // 56*56
#define PIX   8             // pixels per tile
#define NTHREADS 512
#define NT    7             // tiles per block
#define NBLOCKS 448         // 3136 tiles / NT
#define CHUNKS_PER_B 56     // 392 tiles per batch / NT

#define TILE_FLOATS (TT*CC*PIX)      // 18432 floats = 73728 B
#define NCG   64                     // c-groups = NTHREADS/PIX
#define PITCH 11                     // partials pitch (conflict-free, >= TT+1)

// SMEM layout (float offsets)
#define OFF_BUF0  0
#define OFF_BUF1  (TILE_FLOATS)                  // 18432
#define OFF_WC    (2*TILE_FLOATS)                // 36864
#define OFF_WO    (OFF_WC + CC)                  // 37120
#define OFF_PART  (OFF_WO + CC)                  // 37376  [NCG][PITCH][PIX]
#define OFF_SCOR  (OFF_PART + NCG*PITCH*PIX)     // 43008  [TT][PIX]
#define OFF_CENT  (OFF_SCOR + TT*PIX)            // 43080  [PIX]
#define SMEM_FLOATS (OFF_CENT + PIX)             // 43088
#define SMEM_BYTES  (SMEM_FLOATS * 4)            // 172352 B

__device__ __forceinline__ void issue_tile(uint32_t smem_dst_bytes,
                                           const float* __restrict__ src,
                                           int tid)
{
    // src = seq + b*CC*HWHW + pix0 ; thread (c = tid>>1, q = tid&1) loads
    // 16 bytes of row (t, c) for t = 0..8.
    const int q = tid & 1;
    const int c = tid >> 1;                      // 0..255
    const float* g = src + (size_t)c * HWHW + q * 4;
    uint32_t s = smem_dst_bytes + (uint32_t)((c * PIX + q * 4) * 4);
    #pragma unroll
    for (int t = 0; t < TT; ++t) {
        asm volatile("cp.async.cg.shared.global [%0], [%1], 16;\n"
                     :: "r"(s), "l"(g) : "memory");
        g += (size_t)BB * CC * HWHW;             // next t
        s += CC * PIX * 4;                       // 8192 bytes per t-slab
    }
}

__global__ __launch_bounds__(NTHREADS, 1)
void tfma_kernel(const float* __restrict__ seq,
                 const float* __restrict__ w,
                 const float* __restrict__ bptr,
                 const float* __restrict__ gptr,
                 float* __restrict__ out)
{
    extern __shared__ float sm[];
    float* wc   = sm + OFF_WC;
    float* wo   = sm + OFF_WO;
    float* part = sm + OFF_PART;
    float* scor = sm + OFF_SCOR;
    float* cent = sm + OFF_CENT;
    const uint32_t smem_base = (uint32_t)__cvta_generic_to_shared(sm);

    const int tid   = threadIdx.x;
    const int bidx  = blockIdx.x / CHUNKS_PER_B;
    const int chunk = blockIdx.x % CHUNKS_PER_B;

    const float* tbase = seq + (size_t)bidx * CC * HWHW;   // + pix0 per tile
    float*       obase0 = out + (size_t)bidx * CC * HWHW;

    // stage weights (consumed after first barrier)
    if (tid < CC) {
        wc[tid] = w[tid];
        wo[tid] = w[CC + tid];
    }

    const int p  = tid & (PIX - 1);
    const int cg = tid >> 3;                     // 0..63

    // ---- prologue: fire tile 0 ----
    issue_tile(smem_base + OFF_BUF0 * 4, tbase + (size_t)(chunk * NT) * PIX, tid);
    asm volatile("cp.async.commit_group;\n" ::: "memory");

    for (int k = 0; k < NT; ++k) {
        // fire tile k+1 into the other buffer (its previous contents were
        // consumed at iteration k-1; end-of-iter barrier protects reuse)
        if (k + 1 < NT) {
            const int pix1 = (chunk * NT + k + 1) * PIX;
            issue_tile(smem_base + ((k & 1) ? OFF_BUF0 : OFF_BUF1) * 4,
                       tbase + pix1, tid);
        }
        asm volatile("cp.async.commit_group;\n" ::: "memory");
        asm volatile("cp.async.wait_group 1;\n" ::: "memory");
        __syncthreads();

        const float* tile = sm + ((k & 1) ? OFF_BUF1 : OFF_BUF0);
        const int pix0 = (chunk * NT + k) * PIX;

        // ---- phase 2: partial score reductions over C ----
        {
            float acc[TT];
            float accc = 0.f;
            #pragma unroll
            for (int t = 0; t < TT; ++t) acc[t] = 0.f;

            #pragma unroll
            for (int ci = 0; ci < CC / NCG; ++ci) {      // 4 iterations
                const int c  = cg + ci * NCG;
                const float wot = wo[c];
                const float wct = wc[c];
                #pragma unroll
                for (int t = 0; t < TT; ++t) {
                    const float v = tile[(t * CC + c) * PIX + p];
                    acc[t] = fmaf(v, wot, acc[t]);
                    if (t == TT / 2) accc = fmaf(v, wct, accc);
                }
            }
            #pragma unroll
            for (int t = 0; t < TT; ++t)
                part[(cg * PITCH + t) * PIX + p] = acc[t];
            part[(cg * PITCH + TT) * PIX + p] = accc;
        }
        __syncthreads();

        // ---- cross-group reduce (80 threads) ----
        if (tid < TT * PIX) {
            const int t  = tid >> 3;
            const int pp = tid & 7;
            float s = 0.f;
            #pragma unroll
            for (int g = 0; g < NCG; ++g)
                s += part[(g * PITCH + t) * PIX + pp];
            scor[t * PIX + pp] = s;
        } else if (tid < TT * PIX + PIX) {
            const int pp = tid - TT * PIX;
            float s = 0.f;
            #pragma unroll
            for (int g = 0; g < NCG; ++g)
                s += part[(g * PITCH + TT) * PIX + pp];
            cent[pp] = s;
        }
        __syncthreads();

        // ---- softmax over T per pixel ----
        if (tid < PIX) {
            const float bv = bptr[0];
            const float cv = cent[tid];
            float sc[TT];
            float m = -1e30f;
            #pragma unroll
            for (int t = 0; t < TT; ++t) {
                sc[t] = scor[t * PIX + tid] + cv + bv;
                m = fmaxf(m, sc[t]);
            }
            float sum = 0.f;
            #pragma unroll
            for (int t = 0; t < TT; ++t) {
                sc[t] = __expf(sc[t] - m);
                sum += sc[t];
            }
            const float inv = 1.f / sum;
            #pragma unroll
            for (int t = 0; t < TT; ++t)
                scor[t * PIX + tid] = sc[t] * inv;       // attn weights
        }
        __syncthreads();

        // ---- phase 3: attended sum + residual, write out ----
        {
            float a[TT];
            #pragma unroll
            for (int t = 0; t < TT; ++t) a[t] = scor[t * PIX + p];
            const float gamma = gptr[0];
            float* ob = obase0 + pix0 + p;

            #pragma unroll
            for (int ci = 0; ci < CC / NCG; ++ci) {      // 4 outputs per thread
                const int c = cg + ci * NCG;
                float s  = 0.f;
                float cv = 0.f;
                #pragma unroll
                for (int t = 0; t < TT; ++t) {
                    const float v = tile[(t * CC + c) * PIX + p];
                    s = fmaf(a[t], v, s);
                    if (t == TT / 2) cv = v;
                }
                ob[(size_t)c * HWHW] = cv + gamma * s;
            }
        }
        __syncthreads();   // buffer + part/scor reuse protection
    }
}

extern "C" void kernel_launch(void* const* d_in, const int* in_sizes, int n_in,
                              void* d_out, int out_size)
{
    (void)in_sizes; (void)n_in; (void)out_size;
    const float* seq   = (const float*)d_in[0];
    const float* w     = (const float*)d_in[1];
    const float* bv    = (const float*)d_in[2];
    const float* gamma = (const float*)d_in[3];
    float* out = (float*)d_out;

    cudaFuncSetAttribute(tfma_kernel,
                         cudaFuncAttributeMaxDynamicSharedMemorySize, SMEM_BYTES);

    tfma_kernel<<<NBLOCKS, NTHREADS, SMEM_BYTES>>>(seq, w, bv, gamma, out);
}

// round 3
// speedup vs baseline: 2.0925x; 1.3247x over previous
#include <cuda_runtime.h>
#include <cuda.h>
#include <cstdint>

// Problem constants
#define TT    9
#define BB    8
#define CC    256
#define HWHW  3136
#define PIX   8
#define NTHREADS 512
#define NT    7
#define CHUNKS_PER_B 56
#define NBLOCKS 448

#define TILE_FLOATS (TT*CC*PIX)          // 18432 floats = 73728 B
#define TILE_BYTES  (TILE_FLOATS*4)

// SMEM layout (float offsets)
#define OFF_BUF0  0
#define OFF_BUF1  (TILE_FLOATS)          // 18432
#define OFF_WC    (2*TILE_FLOATS)        // 36864
#define OFF_WO    (OFF_WC + CC)          // 37120
#define OFF_PART  (OFF_WO + CC)          // 37376  [16 warps][80]
#define OFF_SCOR  (OFF_PART + 16*80)     // 38656  [80] (t=0..8 scores, t=9 center)
#define OFF_MBAR  (OFF_SCOR + 80)        // 38736  (2 x u64; 8B aligned: 38736*4=154944)
#define SMEM_FLOATS (OFF_MBAR + 4)
#define SMEM_BYTES  (SMEM_FLOATS * 4)

// ---------------- mbarrier / TMA PTX helpers ----------------
#define MBAR_INIT(addr, cnt) \
    asm volatile("mbarrier.init.shared.b64 [%0], %1;" :: "r"(addr), "r"(cnt) : "memory")
#define MBAR_EXPECT_TX(addr, bytes) \
    asm volatile("mbarrier.arrive.expect_tx.shared.b64 _, [%0], %1;" :: "r"(addr), "r"(bytes) : "memory")
#define MBAR_WAIT(addr, parity) do {                                           \
    asm volatile("{\n\t.reg .pred P;\n\t"                                      \
        "WL_%=:\n\t"                                                           \
        "mbarrier.try_wait.parity.acquire.cta.shared::cta.b64 P, [%0], %1, 0x989680;\n\t" \
        "@P bra WD_%=;\n\t"                                                    \
        "bra WL_%=;\n\t"                                                       \
        "WD_%=:\n\t}"                                                          \
        :: "r"(addr), "r"(parity) : "memory");                                 \
} while (0)

__device__ __forceinline__ void tma_load_tile(uint32_t dst, const CUtensorMap* map,
                                              int x, int y, int z, int ww, uint32_t mbar)
{
    asm volatile(
        "cp.async.bulk.tensor.4d.shared::cta.global.tile.mbarrier::complete_tx::bytes "
        "[%0], [%1, {%2, %3, %4, %5}], [%6];"
        :: "r"(dst), "l"(map), "r"(x), "r"(y), "r"(z), "r"(ww), "r"(mbar)
        : "memory");
}

// ---------------- TMA kernel ----------------
__global__ __launch_bounds__(NTHREADS, 1)
void tfma_tma_kernel(const __grid_constant__ CUtensorMap tmap,
                     const float* __restrict__ wptr,
                     const float* __restrict__ bptr,
                     const float* __restrict__ gptr,
                     float* __restrict__ out)
{
    extern __shared__ float sm[];
    float* wc   = sm + OFF_WC;
    float* wo   = sm + OFF_WO;
    float* part = sm + OFF_PART;
    float* scor = sm + OFF_SCOR;
    const uint32_t smem_base = (uint32_t)__cvta_generic_to_shared(sm);
    const uint32_t mbar0 = smem_base + OFF_MBAR * 4;
    const uint32_t mbar1 = mbar0 + 8;

    const int tid   = threadIdx.x;
    const int lane  = tid & 31;
    const int wrp   = tid >> 5;
    const int p     = tid & (PIX - 1);
    const int cg    = tid >> 3;                 // 0..63
    const int bidx  = blockIdx.x / CHUNKS_PER_B;
    const int chunk = blockIdx.x % CHUNKS_PER_B;
    const int pixbase = chunk * NT * PIX;

    if (tid < CC) {
        wc[tid] = wptr[tid];
        wo[tid] = wptr[CC + tid];
    }
    if (tid == 0) {
        MBAR_INIT(mbar0, 1);
        MBAR_INIT(mbar1, 1);
    }
    __syncthreads();

    // prologue: tile 0 -> buf0 / mbar0
    if (tid == 0) {
        MBAR_EXPECT_TX(mbar0, TILE_BYTES);
        tma_load_tile(smem_base + OFF_BUF0 * 4, &tmap, pixbase, 0, bidx, 0, mbar0);
    }

    const float bv    = bptr[0];
    const float gamma = gptr[0];
    float* obase0 = out + (size_t)bidx * CC * HWHW;

    for (int k = 0; k < NT; ++k) {
        // fire tile k+1 into the other buffer (freed by end-of-iter k-1 barrier)
        if (k + 1 < NT && tid == 0) {
            const uint32_t mb  = (k & 1) ? mbar0 : mbar1;
            const uint32_t dst = smem_base + ((k & 1) ? OFF_BUF0 : OFF_BUF1) * 4;
            MBAR_EXPECT_TX(mb, TILE_BYTES);
            tma_load_tile(dst, &tmap, pixbase + (k + 1) * PIX, 0, bidx, 0, mb);
        }

        MBAR_WAIT((k & 1) ? mbar1 : mbar0, (k >> 1) & 1);

        const float* tile = sm + ((k & 1) ? OFF_BUF1 : OFF_BUF0);
        const int pix0 = pixbase + k * PIX;

        // ---- phase 2: score partials over C, warp-shuffle reduced ----
        {
            float acc[TT];
            float accc = 0.f;
            #pragma unroll
            for (int t = 0; t < TT; ++t) acc[t] = 0.f;

            #pragma unroll
            for (int ci = 0; ci < 4; ++ci) {
                const int c  = cg + (ci << 6);
                const float wot = wo[c];
                const float wct = wc[c];
                #pragma unroll
                for (int t = 0; t < TT; ++t) {
                    const float v = tile[(t * CC + c) * PIX + p];
                    acc[t] = fmaf(v, wot, acc[t]);
                    if (t == TT / 2) accc = fmaf(v, wct, accc);
                }
            }
            // reduce across the 4 same-pixel lanes (xor 8, 16)
            #pragma unroll
            for (int t = 0; t < TT; ++t) {
                acc[t] += __shfl_xor_sync(0xffffffffu, acc[t], 8);
                acc[t] += __shfl_xor_sync(0xffffffffu, acc[t], 16);
            }
            accc += __shfl_xor_sync(0xffffffffu, accc, 8);
            accc += __shfl_xor_sync(0xffffffffu, accc, 16);

            if (lane < PIX) {
                #pragma unroll
                for (int t = 0; t < TT; ++t)
                    part[wrp * 80 + t * PIX + lane] = acc[t];
                part[wrp * 80 + TT * PIX + lane] = accc;
            }
        }
        __syncthreads();

        // ---- cross-warp reduce: 80 threads, one value each ----
        if (tid < 80) {
            float s = 0.f;
            #pragma unroll
            for (int g = 0; g < 16; ++g) s += part[g * 80 + tid];
            scor[tid] = s;
        }
        __syncthreads();

        // ---- phase 3: per-thread softmax + attended sum + residual ----
        {
            const float centv = scor[TT * PIX + p];
            float a[TT];
            float m = -1e30f;
            #pragma unroll
            for (int t = 0; t < TT; ++t) {
                a[t] = scor[t * PIX + p] + centv + bv;
                m = fmaxf(m, a[t]);
            }
            float sum = 0.f;
            #pragma unroll
            for (int t = 0; t < TT; ++t) {
                a[t] = __expf(a[t] - m);
                sum += a[t];
            }
            const float inv = 1.f / sum;
            #pragma unroll
            for (int t = 0; t < TT; ++t) a[t] *= inv;

            float* ob = obase0 + pix0 + p;
            #pragma unroll
            for (int ci = 0; ci < 4; ++ci) {
                const int c = cg + (ci << 6);
                float s  = 0.f;
                float cv = 0.f;
                #pragma unroll
                for (int t = 0; t < TT; ++t) {
                    const float v = tile[(t * CC + c) * PIX + p];
                    s = fmaf(a[t], v, s);
                    if (t == TT / 2) cv = v;
                }
                ob[(size_t)c * HWHW] = cv + gamma * s;
            }
        }
        __syncthreads();   // tile buffer + part/scor reuse protection
    }
}

// ---------------- fallback kernel (proven R2 cp.async path) ----------------
#define FB_NCG 64
__device__ __forceinline__ void fb_issue_tile(uint32_t smem_dst_bytes,
                                              const float* __restrict__ src, int tid)
{
    const int q = tid & 1;
    const int c = tid >> 1;
    const float* g = src + (size_t)c * HWHW + q * 4;
    uint32_t s = smem_dst_bytes + (uint32_t)((c * PIX + q * 4) * 4);
    #pragma unroll
    for (int t = 0; t < TT; ++t) {
        asm volatile("cp.async.cg.shared.global [%0], [%1], 16;\n"
                     :: "r"(s), "l"(g) : "memory");
        g += (size_t)BB * CC * HWHW;
        s += CC * PIX * 4;
    }
}

__global__ __launch_bounds__(NTHREADS, 1)
void tfma_fb_kernel(const float* __restrict__ seq,
                    const float* __restrict__ wptr,
                    const float* __restrict__ bptr,
                    const float* __restrict__ gptr,
                    float* __restrict__ out)
{
    extern __shared__ float sm[];
    float* wc   = sm + OFF_WC;
    float* wo   = sm + OFF_WO;
    float* part = sm + OFF_PART;
    float* scor = sm + OFF_SCOR;
    const uint32_t smem_base = (uint32_t)__cvta_generic_to_shared(sm);

    const int tid   = threadIdx.x;
    const int lane  = tid & 31;
    const int wrp   = tid >> 5;
    const int p     = tid & (PIX - 1);
    const int cg    = tid >> 3;
    const int bidx  = blockIdx.x / CHUNKS_PER_B;
    const int chunk = blockIdx.x % CHUNKS_PER_B;
    const float* tbase = seq + (size_t)bidx * CC * HWHW;

    if (tid < CC) { wc[tid] = wptr[tid]; wo[tid] = wptr[CC + tid]; }

    fb_issue_tile(smem_base + OFF_BUF0 * 4, tbase + (size_t)(chunk * NT) * PIX, tid);
    asm volatile("cp.async.commit_group;\n" ::: "memory");

    const float bv    = bptr[0];
    const float gamma = gptr[0];
    float* obase0 = out + (size_t)bidx * CC * HWHW;

    for (int k = 0; k < NT; ++k) {
        if (k + 1 < NT)
            fb_issue_tile(smem_base + ((k & 1) ? OFF_BUF0 : OFF_BUF1) * 4,
                          tbase + (size_t)((chunk * NT + k + 1) * PIX), tid);
        asm volatile("cp.async.commit_group;\n" ::: "memory");
        asm volatile("cp.async.wait_group 1;\n" ::: "memory");
        __syncthreads();

        const float* tile = sm + ((k & 1) ? OFF_BUF1 : OFF_BUF0);
        const int pix0 = (chunk * NT + k) * PIX;

        float acc[TT]; float accc = 0.f;
        #pragma unroll
        for (int t = 0; t < TT; ++t) acc[t] = 0.f;
        #pragma unroll
        for (int ci = 0; ci < 4; ++ci) {
            const int c = cg + (ci << 6);
            const float wot = wo[c], wct = wc[c];
            #pragma unroll
            for (int t = 0; t < TT; ++t) {
                const float v = tile[(t * CC + c) * PIX + p];
                acc[t] = fmaf(v, wot, acc[t]);
                if (t == TT / 2) accc = fmaf(v, wct, accc);
            }
        }
        #pragma unroll
        for (int t = 0; t < TT; ++t) {
            acc[t] += __shfl_xor_sync(0xffffffffu, acc[t], 8);
            acc[t] += __shfl_xor_sync(0xffffffffu, acc[t], 16);
        }
        accc += __shfl_xor_sync(0xffffffffu, accc, 8);
        accc += __shfl_xor_sync(0xffffffffu, accc, 16);
        if (lane < PIX) {
            #pragma unroll
            for (int t = 0; t < TT; ++t) part[wrp * 80 + t * PIX + lane] = acc[t];
            part[wrp * 80 + TT * PIX + lane] = accc;
        }
        __syncthreads();
        if (tid < 80) {
            float s = 0.f;
            #pragma unroll
            for (int g = 0; g < 16; ++g) s += part[g * 80 + tid];
            scor[tid] = s;
        }
        __syncthreads();
        {
            const float centv = scor[TT * PIX + p];
            float a[TT]; float m = -1e30f;
            #pragma unroll
            for (int t = 0; t < TT; ++t) { a[t] = scor[t * PIX + p] + centv + bv; m = fmaxf(m, a[t]); }
            float sum = 0.f;
            #pragma unroll
            for (int t = 0; t < TT; ++t) { a[t] = __expf(a[t] - m); sum += a[t]; }
            const float inv = 1.f / sum;
            #pragma unroll
            for (int t = 0; t < TT; ++t) a[t] *= inv;

            float* ob = obase0 + pix0 + p;
            #pragma unroll
            for (int ci = 0; ci < 4; ++ci) {
                const int c = cg + (ci << 6);
                float s = 0.f, cv = 0.f;
                #pragma unroll
                for (int t = 0; t < TT; ++t) {
                    const float v = tile[(t * CC + c) * PIX + p];
                    s = fmaf(a[t], v, s);
                    if (t == TT / 2) cv = v;
                }
                ob[(size_t)c * HWHW] = cv + gamma * s;
            }
        }
        __syncthreads();
    }
}

// ---------------- host ----------------
typedef CUresult (*EncodeTiledFn)(CUtensorMap*, CUtensorMapDataType, cuuint32_t, void*,
                                  const cuuint64_t*, const cuuint64_t*,
                                  const cuuint32_t*, const cuuint32_t*,
                                  CUtensorMapInterleave, CUtensorMapSwizzle,
                                  CUtensorMapL2promotion, CUtensorMapFloatOOBfill);

extern "C" void kernel_launch(void* const* d_in, const int* in_sizes, int n_in,
                              void* d_out, int out_size)
{
    (void)in_sizes; (void)n_in; (void)out_size;
    const float* seq   = (const float*)d_in[0];
    const float* w     = (const float*)d_in[1];
    const float* bv    = (const float*)d_in[2];
    const float* gamma = (const float*)d_in[3];
    float* out = (float*)d_out;

    // Resolve cuTensorMapEncodeTiled via cudart (avoids -lcuda link dependency)
    void* fn = nullptr;
    cudaDriverEntryPointQueryResult qr = cudaDriverEntryPointSymbolNotFound;
    cudaGetDriverEntryPointByVersion("cuTensorMapEncodeTiled", &fn, 12000,
                                     cudaEnableDefault, &qr);

    bool tma_ok = false;
    CUtensorMap tmap;
    if (fn && qr == cudaDriverEntryPointSuccess) {
        cuuint64_t dims[4]    = {HWHW, CC, BB, TT};
        cuuint64_t strides[3] = {(cuuint64_t)HWHW * 4,
                                 (cuuint64_t)CC * HWHW * 4,
                                 (cuuint64_t)BB * CC * HWHW * 4};
        cuuint32_t box[4]     = {PIX, CC, 1, TT};
        cuuint32_t estr[4]    = {1, 1, 1, 1};
        CUresult r = ((EncodeTiledFn)fn)(
            &tmap, CU_TENSOR_MAP_DATA_TYPE_FLOAT32, 4, (void*)seq,
            dims, strides, box, estr,
            CU_TENSOR_MAP_INTERLEAVE_NONE, CU_TENSOR_MAP_SWIZZLE_NONE,
            CU_TENSOR_MAP_L2_PROMOTION_L2_128B, CU_TENSOR_MAP_FLOAT_OOB_FILL_NONE);
        tma_ok = (r == CUDA_SUCCESS);
    }

    if (tma_ok) {
        cudaFuncSetAttribute(tfma_tma_kernel,
                             cudaFuncAttributeMaxDynamicSharedMemorySize, SMEM_BYTES);
        tfma_tma_kernel<<<NBLOCKS, NTHREADS, SMEM_BYTES>>>(tmap, w, bv, gamma, out);
    } else {
        cudaFuncSetAttribute(tfma_fb_kernel,
                             cudaFuncAttributeMaxDynamicSharedMemorySize, SMEM_BYTES);
        tfma_fb_kernel<<<NBLOCKS, NTHREADS, SMEM_BYTES>>>(seq, w, bv, gamma, out);
    }
}